// round 14
// baseline (speedup 1.0000x reference)
#include <cuda_runtime.h>
#include <math.h>
#include <stdint.h>

#define BB 256
#define NN 128
#define DD 564
#define NCLS 31
#define KP 544          // padded quadratic-dim count (512 lat + 18 smalls + 14 pad)
#define TOK (BB*NN)
#define TSTRIDE 136     // padded tile row stride (conflict-free mma fragment loads)

// ---------------- device scratch (static: allocations are forbidden) ----------------
__device__ float  g_vp[TOK*KP];
__device__ float  g_vt[TOK*KP];
__device__ float  g_n2p[TOK];
__device__ float  g_n2t[TOK];
__device__ float  g_logZ[TOK];
__device__ int    g_cls[TOK];
__device__ double g_acc[7];

__device__ __forceinline__ unsigned fkey(float v) {
    unsigned u = __float_as_uint(v);
    return (u & 0x80000000u) ? ~u : (u | 0x80000000u);
}
__device__ __forceinline__ float unfkey(unsigned k) {
    return __uint_as_float((k & 0x80000000u) ? (k & 0x7fffffffu) : ~k);
}
__device__ __forceinline__ unsigned f2tf32(float x) {
    unsigned r;
    asm("cvt.rna.tf32.f32 %0, %1;" : "=r"(r) : "f"(x));
    return r;
}

// ---------------- prep ----------------
__global__ void prep_kernel(const float* __restrict__ pred, const float* __restrict__ target)
{
    if (blockIdx.x == 0 && threadIdx.x < 7) g_acc[threadIdx.x] = 0.0;

    int w    = (blockIdx.x * blockDim.x + threadIdx.x) >> 5;
    int lane = threadIdx.x & 31;
    bool isT = (w >= TOK);
    int tok  = isT ? (w - TOK) : w;

    const float* src = (isT ? target : pred) + (size_t)tok * DD;
    float*       dst = (isT ? g_vt : g_vp) + (size_t)tok * KP;

    const float s512 = 0.04419417382415922f;   // 1/sqrt(512)
    float ss = 0.f;

    const float2* s2 = (const float2*)(src + 46);
    float2*       d2 = (float2*)dst;
    #pragma unroll 4
    for (int i = lane; i < 256; i += 32) {
        float2 v = s2[i];
        float a = v.x * s512, c = v.y * s512;
        d2[i] = make_float2(a, c);
        ss = fmaf(a, a, ss);
        ss = fmaf(c, c, ss);
    }

    if (lane < 18) {
        int d = (lane < 9) ? (31 + lane) : ((lane < 12) ? (34 + lane) : (546 + lane));
        float sc = (lane < 12) ? 0.5773502691896258f : 0.4082482904638630f;
        float vv = src[d] * sc;
        dst[512 + lane] = vv;
        ss = fmaf(vv, vv, ss);
    } else {
        dst[512 + lane] = 0.f;
    }

    #pragma unroll
    for (int o = 16; o; o >>= 1) ss += __shfl_xor_sync(0xffffffffu, ss, o);
    if (lane == 0) (isT ? g_n2t : g_n2p)[tok] = ss;

    float v = (lane < NCLS) ? src[lane] : -INFINITY;
    if (isT) {
        float bv = v; int bi = (lane < NCLS) ? lane : NCLS;
        #pragma unroll
        for (int o = 16; o; o >>= 1) {
            float ov = __shfl_xor_sync(0xffffffffu, bv, o);
            int   oi = __shfl_xor_sync(0xffffffffu, bi, o);
            if (ov > bv || (ov == bv && oi < bi)) { bv = ov; bi = oi; }
        }
        if (lane == 0) g_cls[tok] = bi;
    } else {
        float m = v;
        #pragma unroll
        for (int o = 16; o; o >>= 1) m = fmaxf(m, __shfl_xor_sync(0xffffffffu, m, o));
        float e = (lane < NCLS) ? expf(v - m) : 0.f;
        #pragma unroll
        for (int o = 16; o; o >>= 1) e += __shfl_xor_sync(0xffffffffu, e, o);
        if (lane == 0) g_logZ[tok] = m + logf(e);
    }
}

// -------- fused cost(tf32 MMA) + JV-LSA + matched loss: one block per batch --------
// dyn smem: C[128*128] floats, then tiles[2*16*TSTRIDE] floats
__global__ void __launch_bounds__(256, 2) cost_lsa_kernel(const float* __restrict__ pred)
{
    extern __shared__ __align__(16) float dyn[];
    float* C     = dyn;              // 16384 floats
    float* tiles = dyn + 16384;      // 4352 floats (GEMM tiles; later class table)

    __shared__ float s_n2p[NN], s_n2t[NN], s_logZ[NN];
    __shared__ int   s_cls[NN];
    __shared__ int   p_sh[NN+1];
    __shared__ int   way_sh[NN+1];
    __shared__ int2  wv_sh[NN+1];
    __shared__ int   imin_sh[NN];
    __shared__ int   rs_sh[NN];
    __shared__ int   free_sh[NN];
    __shared__ double s_part[7];

    int b   = blockIdx.x;
    int tid = threadIdx.x;
    int wid = tid >> 5;
    size_t base = (size_t)b * NN;

    if (tid < 7) s_part[tid] = 0.0;
    if (tid < NN) {
        s_n2p[tid]  = g_n2p[base + tid];
        s_n2t[tid]  = g_n2t[base + tid];
        s_logZ[tid] = g_logZ[base + tid];
        s_cls[tid]  = g_cls[base + tid];
        rs_sh[tid]  = 0;
        p_sh[tid]   = 0;
    }
    if (tid == NN) p_sh[NN] = 0;

    // ---- GEMM via mma.sync tf32: D[p][t] = vp[p] . vt[t] over 544 dims ----
    int wrp = tid >> 5;
    int t5  = tid & 31;
    int qr  = t5 >> 2;     // 0..7
    int qc  = t5 & 3;      // 0..3
    int m0  = wrp * 16;

    float d[16][4];
    #pragma unroll
    for (int nt = 0; nt < 16; nt++)
        #pragma unroll
        for (int c = 0; c < 4; c++) d[nt][c] = 0.f;

    const float* vp = g_vp + base * KP;
    const float* vt = g_vt + base * KP;
    float* As = tiles;                     // [16][TSTRIDE] k-major
    float* Bs = tiles + 16 * TSTRIDE;

    int r  = tid >> 1;
    int kc = (tid & 1) * 8;

    for (int k0 = 0; k0 < KP; k0 += 16) {
        __syncthreads();
        float4 a0 = *(const float4*)(vp + (size_t)r * KP + k0 + kc);
        float4 a1 = *(const float4*)(vp + (size_t)r * KP + k0 + kc + 4);
        float4 b0 = *(const float4*)(vt + (size_t)r * KP + k0 + kc);
        float4 b1 = *(const float4*)(vt + (size_t)r * KP + k0 + kc + 4);
        float av[8] = {a0.x,a0.y,a0.z,a0.w,a1.x,a1.y,a1.z,a1.w};
        float bv[8] = {b0.x,b0.y,b0.z,b0.w,b1.x,b1.y,b1.z,b1.w};
        #pragma unroll
        for (int i = 0; i < 8; i++) {
            As[(kc+i)*TSTRIDE + r] = __uint_as_float(f2tf32(av[i]));
            Bs[(kc+i)*TSTRIDE + r] = __uint_as_float(f2tf32(bv[i]));
        }
        __syncthreads();

        #pragma unroll
        for (int ks = 0; ks < 2; ks++) {
            int kb = ks * 8;
            unsigned fa0 = __float_as_uint(As[(kb+qc  )*TSTRIDE + m0 + qr    ]);
            unsigned fa1 = __float_as_uint(As[(kb+qc  )*TSTRIDE + m0 + qr + 8]);
            unsigned fa2 = __float_as_uint(As[(kb+qc+4)*TSTRIDE + m0 + qr    ]);
            unsigned fa3 = __float_as_uint(As[(kb+qc+4)*TSTRIDE + m0 + qr + 8]);
            #pragma unroll
            for (int nt = 0; nt < 16; nt++) {
                int n0 = nt * 8;
                unsigned fb0 = __float_as_uint(Bs[(kb+qc  )*TSTRIDE + n0 + qr]);
                unsigned fb1 = __float_as_uint(Bs[(kb+qc+4)*TSTRIDE + n0 + qr]);
                asm volatile(
                    "mma.sync.aligned.m16n8k8.row.col.f32.tf32.tf32.f32 "
                    "{%0,%1,%2,%3}, {%4,%5,%6,%7}, {%8,%9}, {%0,%1,%2,%3};"
                    : "+f"(d[nt][0]), "+f"(d[nt][1]), "+f"(d[nt][2]), "+f"(d[nt][3])
                    : "r"(fa0), "r"(fa1), "r"(fa2), "r"(fa3), "r"(fb0), "r"(fb1));
            }
        }
    }

    // class-logit table into tiles (persists through LSA for the CE term)
    __syncthreads();
    for (int i = tid; i < NN * NCLS; i += 256) {
        int p = i / NCLS, c = i - p * NCLS;
        tiles[p*32 + c] = pred[(base + p) * DD + c];
    }
    __syncthreads();

    // epilogue: cost into smem C
    {
        int p0 = m0 + qr, p1 = p0 + 8;
        float zp0 = s_logZ[p0], np0 = s_n2p[p0];
        float zp1 = s_logZ[p1], np1 = s_n2p[p1];
        #pragma unroll
        for (int nt = 0; nt < 16; nt++) {
            int j0 = nt*8 + 2*qc, j1 = j0 + 1;
            int   c0 = s_cls[j0],  c1 = s_cls[j1];
            float t0 = s_n2t[j0],  t1 = s_n2t[j1];
            float cs00 = fminf(zp0 - tiles[p0*32 + c0], 18.420680743952367f);
            float cs01 = fminf(zp0 - tiles[p0*32 + c1], 18.420680743952367f);
            float cs10 = fminf(zp1 - tiles[p1*32 + c0], 18.420680743952367f);
            float cs11 = fminf(zp1 - tiles[p1*32 + c1], 18.420680743952367f);
            float2 r0 = make_float2(cs00 + np0 + t0 - 2.0f*d[nt][0],
                                    cs01 + np0 + t1 - 2.0f*d[nt][1]);
            float2 r1 = make_float2(cs10 + np1 + t0 - 2.0f*d[nt][2],
                                    cs11 + np1 + t1 - 2.0f*d[nt][3]);
            *(float2*)(C + p0*NN + j0) = r0;
            *(float2*)(C + p1*NN + j0) = r1;
        }
    }
    __syncthreads();

    // =================== JV LSA, warp 0 only (others wait at barrier) ===================
    if (tid < 32) {
        int lane = tid;

        // 1. column reduction
        float vreg[4];
        float cmin[4] = {INFINITY, INFINITY, INFINITY, INFINITY};
        int   cim[4]  = {0, 0, 0, 0};
        for (int i = 0; i < NN; i++) {
            const float* row = C + i * NN;
            #pragma unroll
            for (int k = 0; k < 4; k++) {
                float c = row[lane + 32*k];
                if (c < cmin[k]) { cmin[k] = c; cim[k] = i; }
            }
        }
        #pragma unroll
        for (int k = 0; k < 4; k++) {
            vreg[k] = cmin[k];
            imin_sh[lane + 32*k] = cim[k];
        }
        __syncwarp();

        if (lane == 0) {
            for (int j = NN - 1; j >= 0; j--) {
                int i1 = imin_sh[j];
                if (rs_sh[i1] == 0) { rs_sh[i1] = j + 1; p_sh[j + 1] = i1 + 1; }
            }
        }
        __syncwarp();

        // 2. reduction transfer + free-row list
        int nfree = 0;
        for (int i = 0; i < NN; i++) {
            int j1 = rs_sh[i];
            if (j1 == 0) {
                if (lane == 0) free_sh[nfree] = i + 1;
                nfree++;
            } else {
                const float* row = C + i * NN;
                float best = INFINITY;
                #pragma unroll
                for (int k = 0; k < 4; k++) {
                    int jm = lane + 32*k;
                    float cur = (jm + 1 == j1) ? INFINITY : (row[jm] - vreg[k]);
                    best = fminf(best, cur);
                }
                float mu = unfkey(__reduce_min_sync(0xffffffffu, fkey(best)));
                #pragma unroll
                for (int k = 0; k < 4; k++)
                    if (lane + 32*k + 1 == j1) vreg[k] -= mu;
            }
        }
        __syncwarp();

        // 2b. greedy pass 2
        {
            int nf2 = 0;
            for (int f = 0; f < nfree; f++) {
                int i = free_sh[f];
                const float* row = C + (i - 1) * NN;
                float bv = INFINITY; int bj = 0x7fffffff;
                #pragma unroll
                for (int k = 0; k < 4; k++) {
                    float cur = row[lane + 32*k] - vreg[k];
                    if (cur < bv) { bv = cur; bj = lane + 32*k + 1; }
                }
                unsigned kk = fkey(bv);
                unsigned mk = __reduce_min_sync(0xffffffffu, kk);
                int j1 = (int)__reduce_min_sync(0xffffffffu, (kk == mk) ? (unsigned)bj : 0xffffffffu);
                if (p_sh[j1] == 0) {
                    if (lane == 0) p_sh[j1] = i;
                } else {
                    if (lane == 0) free_sh[nf2] = i;
                    nf2++;
                }
                __syncwarp();
            }
            nfree = nf2;
        }
        __syncwarp();

        // 3. Dijkstra augmentation
        for (int f = 0; f < nfree; f++) {
            int frow = free_sh[f];
            #pragma unroll
            for (int k = 0; k < 4; k++) {
                int j0m = lane + 32*k;
                int j   = j0m + 1;
                int pj  = p_sh[j];
                int off = pj ? (pj - 1) * NN : -1;
                float wv = pj ? (C[(pj - 1) * NN + j0m] - vreg[k]) : 0.f;
                wv_sh[j] = make_int2(off, __float_as_int(wv));
                way_sh[j] = 0;
            }
            if (lane == 0) p_sh[0] = frow;
            __syncwarp();

            const float* rowf = C + (frow - 1) * NN;
            float minv[4];
            #pragma unroll
            for (int k = 0; k < 4; k++) minv[k] = rowf[lane + 32*k] - vreg[k];

            unsigned used = 0;
            float minVal; int sink;
            while (true) {
                float bv = INFINITY; int bj = 0x7fffffff;
                #pragma unroll
                for (int k = 0; k < 4; k++) {
                    float cand = ((used >> k) & 1) ? INFINITY : minv[k];
                    if (cand < bv) { bv = cand; bj = lane + 32*k + 1; }
                }
                unsigned kk = fkey(bv);
                unsigned mk = __reduce_min_sync(0xffffffffu, kk);
                int j0 = (int)__reduce_min_sync(0xffffffffu, (kk == mk) ? (unsigned)bj : 0xffffffffu);
                minVal = unfkey(mk);

                int2 wv = wv_sh[j0];
                if (wv.x < 0) { sink = j0; break; }
                if (((j0 - 1) & 31) == lane) used |= 1u << ((j0 - 1) >> 5);

                const float* rowi = C + wv.x;
                float r0 = minVal - __int_as_float(wv.y);
                #pragma unroll
                for (int k = 0; k < 4; k++) {
                    if (!((used >> k) & 1)) {
                        float cur = r0 + rowi[lane + 32*k] - vreg[k];
                        if (cur < minv[k]) { minv[k] = cur; way_sh[lane + 32*k + 1] = j0; }
                    }
                }
            }
            __syncwarp();
            #pragma unroll
            for (int k = 0; k < 4; k++)
                if ((used >> k) & 1) vreg[k] -= (minVal - minv[k]);
            if (lane == 0) {
                int jj = sink;
                while (jj) { int w = way_sh[jj]; p_sh[jj] = p_sh[w]; jj = w; }
            }
            __syncwarp();
        }
    }
    __syncthreads();

    // ---------------- matched loss (8 warps x 16 targets), fused ----------------
    {
        int lane = tid & 31;
        for (int t = wid; t < NN; t += 8) {
            int rr = p_sh[t + 1] - 1;       // matched pred row for target t
            size_t ip = base + rr;
            size_t it = base + t;

            const float4* vp4 = (const float4*)(g_vp + ip * KP);
            const float4* vt4 = (const float4*)(g_vt + it * KP);

            float sla = 0.f;
            #pragma unroll
            for (int i = 0; i < 4; i++) {
                float4 a = vp4[lane + 32*i];
                float4 c = vt4[lane + 32*i];
                float dx = a.x - c.x, dy = a.y - c.y, dz = a.z - c.z, dw = a.w - c.w;
                sla = fmaf(dx, dx, sla); sla = fmaf(dy, dy, sla);
                sla = fmaf(dz, dz, sla); sla = fmaf(dw, dw, sla);
            }
            #pragma unroll
            for (int o = 16; o; o >>= 1) sla += __shfl_xor_sync(0xffffffffu, sla, o);

            if (lane < 18) {
                float diff = g_vp[ip*KP + 512 + lane] - g_vt[it*KP + 512 + lane];
                int s = (lane < 3) ? 1 : (lane < 6) ? 2 : (lane < 9) ? 3 : (lane < 12) ? 5 : 4;
                atomicAdd(&s_part[s], (double)(diff * diff));
            }
            if (lane == 0) {
                atomicAdd(&s_part[6], (double)sla);
                float ce = s_logZ[rr] - tiles[rr*32 + s_cls[t]];   // class table still in smem
                atomicAdd(&s_part[0], (double)ce);
            }
        }
    }
    __syncthreads();
    if (tid < 7) atomicAdd(&g_acc[tid], s_part[tid]);
}

// ---------------- finalize ----------------
__global__ void finalize_kernel(float* out, int out_size)
{
    if (threadIdx.x == 0) {
        double denom = 32768.0 + 1e-8;
        double tot = 0.0;
        double st[7];
        for (int i = 0; i < 7; i++) { st[i] = g_acc[i]; tot += st[i]; }
        if (out_size >= 1) out[0] = (float)(tot / denom);
        for (int i = 0; i < 7; i++)
            if (out_size > i + 1) out[i + 1] = (float)(st[i] / denom);
    }
}

// ---------------- launch ----------------
extern "C" void kernel_launch(void* const* d_in, const int* in_sizes, int n_in,
                              void* d_out, int out_size)
{
    const float* pred   = (const float*)d_in[0];
    const float* target = (const float*)d_in[1];

    const int dynBytes = (16384 + 2*16*TSTRIDE) * 4;   // 82944
    cudaFuncSetAttribute(cost_lsa_kernel, cudaFuncAttributeMaxDynamicSharedMemorySize, dynBytes);

    prep_kernel<<<(2*TOK)/8, 256>>>(pred, target);
    cost_lsa_kernel<<<BB, 256, dynBytes>>>(pred);
    finalize_kernel<<<1, 32>>>((float*)d_out, out_size);
}

// round 15
// speedup vs baseline: 1.1971x; 1.1971x over previous
#include <cuda_runtime.h>
#include <math.h>
#include <stdint.h>

#define BB 256
#define NN 128
#define DD 564
#define NCLS 31
#define KP 544          // padded quadratic-dim count (512 lat + 18 smalls + 14 pad)
#define TOK (BB*NN)
#define TSTRIDE 136     // padded tile row stride (conflict-free mma fragment loads)

// ---------------- device scratch (static: allocations are forbidden) ----------------
__device__ float  g_vp[TOK*KP];
__device__ float  g_vt[TOK*KP];
__device__ float  g_n2p[TOK];
__device__ float  g_n2t[TOK];
__device__ float  g_logZ[TOK];
__device__ int    g_cls[TOK];
__device__ int    g_rows[TOK];
__device__ double g_acc[7];

__device__ __forceinline__ unsigned fkey(float v) {
    unsigned u = __float_as_uint(v);
    return (u & 0x80000000u) ? ~u : (u | 0x80000000u);
}
__device__ __forceinline__ float unfkey(unsigned k) {
    return __uint_as_float((k & 0x80000000u) ? (k & 0x7fffffffu) : ~k);
}
__device__ __forceinline__ unsigned f2tf32(float x) {
    unsigned r;
    asm("cvt.rna.tf32.f32 %0, %1;" : "=r"(r) : "f"(x));
    return r;
}

// ---------------- prep ----------------
__global__ void prep_kernel(const float* __restrict__ pred, const float* __restrict__ target)
{
    if (blockIdx.x == 0 && threadIdx.x < 7) g_acc[threadIdx.x] = 0.0;

    int w    = (blockIdx.x * blockDim.x + threadIdx.x) >> 5;
    int lane = threadIdx.x & 31;
    bool isT = (w >= TOK);
    int tok  = isT ? (w - TOK) : w;

    const float* src = (isT ? target : pred) + (size_t)tok * DD;
    float*       dst = (isT ? g_vt : g_vp) + (size_t)tok * KP;

    const float s512 = 0.04419417382415922f;   // 1/sqrt(512)
    float ss = 0.f;

    const float2* s2 = (const float2*)(src + 46);
    float2*       d2 = (float2*)dst;
    #pragma unroll 4
    for (int i = lane; i < 256; i += 32) {
        float2 v = s2[i];
        float a = v.x * s512, c = v.y * s512;
        d2[i] = make_float2(a, c);
        ss = fmaf(a, a, ss);
        ss = fmaf(c, c, ss);
    }

    if (lane < 18) {
        int d = (lane < 9) ? (31 + lane) : ((lane < 12) ? (34 + lane) : (546 + lane));
        float sc = (lane < 12) ? 0.5773502691896258f : 0.4082482904638630f;
        float vv = src[d] * sc;
        dst[512 + lane] = vv;
        ss = fmaf(vv, vv, ss);
    } else {
        dst[512 + lane] = 0.f;
    }

    #pragma unroll
    for (int o = 16; o; o >>= 1) ss += __shfl_xor_sync(0xffffffffu, ss, o);
    if (lane == 0) (isT ? g_n2t : g_n2p)[tok] = ss;

    float v = (lane < NCLS) ? src[lane] : -INFINITY;
    if (isT) {
        float bv = v; int bi = (lane < NCLS) ? lane : NCLS;
        #pragma unroll
        for (int o = 16; o; o >>= 1) {
            float ov = __shfl_xor_sync(0xffffffffu, bv, o);
            int   oi = __shfl_xor_sync(0xffffffffu, bi, o);
            if (ov > bv || (ov == bv && oi < bi)) { bv = ov; bi = oi; }
        }
        if (lane == 0) g_cls[tok] = bi;
    } else {
        float m = v;
        #pragma unroll
        for (int o = 16; o; o >>= 1) m = fmaxf(m, __shfl_xor_sync(0xffffffffu, m, o));
        float e = (lane < NCLS) ? expf(v - m) : 0.f;
        #pragma unroll
        for (int o = 16; o; o >>= 1) e += __shfl_xor_sync(0xffffffffu, e, o);
        if (lane == 0) g_logZ[tok] = m + logf(e);
    }
}

// ---------------- fused cost(tf32 MMA) + JV-LSA: one block per batch ----------------
// dyn smem: C[128*128] floats, then tiles[2*16*TSTRIDE] floats
__global__ void __launch_bounds__(256, 2) cost_lsa_kernel(const float* __restrict__ pred)
{
    extern __shared__ __align__(16) float dyn[];
    float* C     = dyn;              // 16384 floats
    float* tiles = dyn + 16384;      // 4352 floats (also reused as class table)

    __shared__ float s_n2p[NN], s_n2t[NN], s_logZ[NN];
    __shared__ int   s_cls[NN];
    __shared__ int   p_sh[NN+1];
    __shared__ int   way_sh[NN+1];
    __shared__ int2  wv_sh[NN+1];
    __shared__ int   imin_sh[NN];
    __shared__ int   rs_sh[NN];
    __shared__ int   free_sh[NN];

    int b   = blockIdx.x;
    int tid = threadIdx.x;
    size_t base = (size_t)b * NN;

    if (tid < NN) {
        s_n2p[tid]  = g_n2p[base + tid];
        s_n2t[tid]  = g_n2t[base + tid];
        s_logZ[tid] = g_logZ[base + tid];
        s_cls[tid]  = g_cls[base + tid];
        rs_sh[tid]  = 0;
        p_sh[tid]   = 0;
    }
    if (tid == NN) p_sh[NN] = 0;

    // ---- GEMM via mma.sync tf32 ----
    int wrp = tid >> 5;
    int t5  = tid & 31;
    int qr  = t5 >> 2;
    int qc  = t5 & 3;
    int m0  = wrp * 16;

    float d[16][4];
    #pragma unroll
    for (int nt = 0; nt < 16; nt++)
        #pragma unroll
        for (int c = 0; c < 4; c++) d[nt][c] = 0.f;

    const float* vp = g_vp + base * KP;
    const float* vt = g_vt + base * KP;
    float* As = tiles;
    float* Bs = tiles + 16 * TSTRIDE;

    int r  = tid >> 1;
    int kc = (tid & 1) * 8;

    for (int k0 = 0; k0 < KP; k0 += 16) {
        __syncthreads();
        float4 a0 = *(const float4*)(vp + (size_t)r * KP + k0 + kc);
        float4 a1 = *(const float4*)(vp + (size_t)r * KP + k0 + kc + 4);
        float4 b0 = *(const float4*)(vt + (size_t)r * KP + k0 + kc);
        float4 b1 = *(const float4*)(vt + (size_t)r * KP + k0 + kc + 4);
        float av[8] = {a0.x,a0.y,a0.z,a0.w,a1.x,a1.y,a1.z,a1.w};
        float bv[8] = {b0.x,b0.y,b0.z,b0.w,b1.x,b1.y,b1.z,b1.w};
        #pragma unroll
        for (int i = 0; i < 8; i++) {
            As[(kc+i)*TSTRIDE + r] = __uint_as_float(f2tf32(av[i]));
            Bs[(kc+i)*TSTRIDE + r] = __uint_as_float(f2tf32(bv[i]));
        }
        __syncthreads();

        #pragma unroll
        for (int ks = 0; ks < 2; ks++) {
            int kb = ks * 8;
            unsigned fa0 = __float_as_uint(As[(kb+qc  )*TSTRIDE + m0 + qr    ]);
            unsigned fa1 = __float_as_uint(As[(kb+qc  )*TSTRIDE + m0 + qr + 8]);
            unsigned fa2 = __float_as_uint(As[(kb+qc+4)*TSTRIDE + m0 + qr    ]);
            unsigned fa3 = __float_as_uint(As[(kb+qc+4)*TSTRIDE + m0 + qr + 8]);
            #pragma unroll
            for (int nt = 0; nt < 16; nt++) {
                int n0 = nt * 8;
                unsigned fb0 = __float_as_uint(Bs[(kb+qc  )*TSTRIDE + n0 + qr]);
                unsigned fb1 = __float_as_uint(Bs[(kb+qc+4)*TSTRIDE + n0 + qr]);
                asm volatile(
                    "mma.sync.aligned.m16n8k8.row.col.f32.tf32.tf32.f32 "
                    "{%0,%1,%2,%3}, {%4,%5,%6,%7}, {%8,%9}, {%0,%1,%2,%3};"
                    : "+f"(d[nt][0]), "+f"(d[nt][1]), "+f"(d[nt][2]), "+f"(d[nt][3])
                    : "r"(fa0), "r"(fa1), "r"(fa2), "r"(fa3), "r"(fb0), "r"(fb1));
            }
        }
    }

    __syncthreads();
    for (int i = tid; i < NN * NCLS; i += 256) {
        int p = i / NCLS, c = i - p * NCLS;
        tiles[p*32 + c] = pred[(base + p) * DD + c];
    }
    __syncthreads();

    {
        int p0 = m0 + qr, p1 = p0 + 8;
        float zp0 = s_logZ[p0], np0 = s_n2p[p0];
        float zp1 = s_logZ[p1], np1 = s_n2p[p1];
        #pragma unroll
        for (int nt = 0; nt < 16; nt++) {
            int j0 = nt*8 + 2*qc, j1 = j0 + 1;
            int   c0 = s_cls[j0],  c1 = s_cls[j1];
            float t0 = s_n2t[j0],  t1 = s_n2t[j1];
            float cs00 = fminf(zp0 - tiles[p0*32 + c0], 18.420680743952367f);
            float cs01 = fminf(zp0 - tiles[p0*32 + c1], 18.420680743952367f);
            float cs10 = fminf(zp1 - tiles[p1*32 + c0], 18.420680743952367f);
            float cs11 = fminf(zp1 - tiles[p1*32 + c1], 18.420680743952367f);
            float2 r0 = make_float2(cs00 + np0 + t0 - 2.0f*d[nt][0],
                                    cs01 + np0 + t1 - 2.0f*d[nt][1]);
            float2 r1 = make_float2(cs10 + np1 + t0 - 2.0f*d[nt][2],
                                    cs11 + np1 + t1 - 2.0f*d[nt][3]);
            *(float2*)(C + p0*NN + j0) = r0;
            *(float2*)(C + p1*NN + j0) = r1;
        }
    }
    __syncthreads();

    // =================== JV LSA, warp 0 only ===================
    if (tid >= 32) return;
    int lane = tid;

    // ---- 1. column reduction ----
    float vreg[4];
    float cmin[4] = {INFINITY, INFINITY, INFINITY, INFINITY};
    int   cim[4]  = {0, 0, 0, 0};
    for (int i = 0; i < NN; i++) {
        const float* row = C + i * NN;
        #pragma unroll
        for (int k = 0; k < 4; k++) {
            float c = row[lane + 32*k];
            if (c < cmin[k]) { cmin[k] = c; cim[k] = i; }
        }
    }
    #pragma unroll
    for (int k = 0; k < 4; k++) {
        vreg[k] = cmin[k];
        imin_sh[lane + 32*k] = cim[k];
    }
    __syncwarp();

    if (lane == 0) {
        for (int j = NN - 1; j >= 0; j--) {
            int i1 = imin_sh[j];
            if (rs_sh[i1] == 0) { rs_sh[i1] = j + 1; p_sh[j + 1] = i1 + 1; }
        }
    }
    __syncwarp();

    // ---- 2. reduction transfer + free-row list ----
    int nfree = 0;
    for (int i = 0; i < NN; i++) {
        int j1 = rs_sh[i];
        if (j1 == 0) {
            if (lane == 0) free_sh[nfree] = i + 1;
            nfree++;
        } else {
            const float* row = C + i * NN;
            float best = INFINITY;
            #pragma unroll
            for (int k = 0; k < 4; k++) {
                int jm = lane + 32*k;
                float cur = (jm + 1 == j1) ? INFINITY : (row[jm] - vreg[k]);
                best = fminf(best, cur);
            }
            float mu = unfkey(__reduce_min_sync(0xffffffffu, fkey(best)));
            #pragma unroll
            for (int k = 0; k < 4; k++)
                if (lane + 32*k + 1 == j1) vreg[k] -= mu;
        }
    }
    __syncwarp();

    // ---- 2b. ARR: 2 passes, NO requeue (bounded: each row scanned once per pass) ----
    for (int pass = 0; pass < 2; pass++) {
        int nf = 0;
        for (int kf = 0; kf < nfree; kf++) {
            int i = free_sh[kf];
            const float* row = C + (i - 1) * NN;
            // per-lane two smallest
            float v1 = INFINITY, v2 = INFINITY; int j1l = 0, j2l = 0;
            #pragma unroll
            for (int k = 0; k < 4; k++) {
                float cur = row[lane + 32*k] - vreg[k];
                int j = lane + 32*k + 1;
                if (cur < v1) { v2 = v1; j2l = j1l; v1 = cur; j1l = j; }
                else if (cur < v2) { v2 = cur; j2l = j; }
            }
            unsigned k1 = fkey(v1);
            unsigned gk1 = __reduce_min_sync(0xffffffffu, k1);
            int j1 = (int)__reduce_min_sync(0xffffffffu, (k1 == gk1) ? (unsigned)j1l : 0xffffffffu);
            bool own = (j1l == j1);
            float cv = own ? v2 : v1;
            int   cj = own ? j2l : j1l;
            unsigned k2 = fkey(cv);
            unsigned gk2 = __reduce_min_sync(0xffffffffu, k2);
            int j2 = (int)__reduce_min_sync(0xffffffffu, (k2 == gk2) ? (unsigned)cj : 0xffffffffu);
            float umin = unfkey(gk1), usub = unfkey(gk2);

            int i0 = p_sh[j1];
            if (umin < usub) {
                float dd = usub - umin;
                #pragma unroll
                for (int k = 0; k < 4; k++)
                    if (lane + 32*k + 1 == j1) vreg[k] -= dd;
            } else if (i0 > 0) {
                j1 = j2; i0 = p_sh[j2];
            }
            if (lane == 0) p_sh[j1] = i;
            if (i0 > 0) {
                if (lane == 0) free_sh[nf] = i0;   // write idx <= read idx: safe in-place
                nf++;
            }
            __syncwarp();
        }
        nfree = nf;
        __syncwarp();
    }

    // ---- 3. Dijkstra augmentation for remaining free rows ----
    for (int f = 0; f < nfree; f++) {
        int frow = free_sh[f];
        #pragma unroll
        for (int k = 0; k < 4; k++) {
            int j0m = lane + 32*k;
            int j   = j0m + 1;
            int pj  = p_sh[j];
            int off = pj ? (pj - 1) * NN : -1;
            float wv = pj ? (C[(pj - 1) * NN + j0m] - vreg[k]) : 0.f;
            wv_sh[j] = make_int2(off, __float_as_int(wv));
            way_sh[j] = 0;
        }
        if (lane == 0) p_sh[0] = frow;
        __syncwarp();

        const float* rowf = C + (frow - 1) * NN;
        float minv[4];
        #pragma unroll
        for (int k = 0; k < 4; k++) minv[k] = rowf[lane + 32*k] - vreg[k];

        unsigned used = 0;
        float minVal; int sink;
        while (true) {
            float bv = INFINITY; int bj = 0x7fffffff;
            #pragma unroll
            for (int k = 0; k < 4; k++) {
                float cand = ((used >> k) & 1) ? INFINITY : minv[k];
                if (cand < bv) { bv = cand; bj = lane + 32*k + 1; }
            }
            unsigned kk = fkey(bv);
            unsigned mk = __reduce_min_sync(0xffffffffu, kk);
            int j0 = (int)__reduce_min_sync(0xffffffffu, (kk == mk) ? (unsigned)bj : 0xffffffffu);
            minVal = unfkey(mk);

            int2 wv = wv_sh[j0];
            if (wv.x < 0) { sink = j0; break; }
            if (((j0 - 1) & 31) == lane) used |= 1u << ((j0 - 1) >> 5);

            const float* rowi = C + wv.x;
            float r0 = minVal - __int_as_float(wv.y);
            #pragma unroll
            for (int k = 0; k < 4; k++) {
                if (!((used >> k) & 1)) {
                    float cur = r0 + rowi[lane + 32*k] - vreg[k];
                    if (cur < minv[k]) { minv[k] = cur; way_sh[lane + 32*k + 1] = j0; }
                }
            }
        }
        __syncwarp();
        #pragma unroll
        for (int k = 0; k < 4; k++)
            if ((used >> k) & 1) vreg[k] -= (minVal - minv[k]);
        if (lane == 0) {
            int jj = sink;
            while (jj) { int w = way_sh[jj]; p_sh[jj] = p_sh[w]; jj = w; }
        }
        __syncwarp();
    }

    #pragma unroll
    for (int k = 0; k < 4; k++) {
        int j = lane + 32*k;
        g_rows[b*NN + j] = p_sh[j + 1] - 1;
    }
}

// ---------------- matched loss ----------------
__global__ void loss_kernel(const float* __restrict__ pred)
{
    __shared__ double s_part[7];
    if (threadIdx.x < 7) s_part[threadIdx.x] = 0.0;
    __syncthreads();

    int gw   = (blockIdx.x * blockDim.x + threadIdx.x) >> 5;
    int lane = threadIdx.x & 31;
    int b = gw >> 7;
    int r = g_rows[gw];
    size_t ip = (size_t)b * NN + r;
    size_t it = (size_t)gw;

    const float4* vp = (const float4*)(g_vp + ip * KP);
    const float4* vt = (const float4*)(g_vt + it * KP);

    float sla = 0.f;
    #pragma unroll
    for (int i = 0; i < 4; i++) {
        float4 a = vp[lane + 32*i];
        float4 c = vt[lane + 32*i];
        float dx = a.x - c.x, dy = a.y - c.y, dz = a.z - c.z, dw = a.w - c.w;
        sla = fmaf(dx, dx, sla); sla = fmaf(dy, dy, sla);
        sla = fmaf(dz, dz, sla); sla = fmaf(dw, dw, sla);
    }
    #pragma unroll
    for (int o = 16; o; o >>= 1) sla += __shfl_xor_sync(0xffffffffu, sla, o);

    if (lane < 18) {
        float diff = g_vp[ip*KP + 512 + lane] - g_vt[it*KP + 512 + lane];
        int s = (lane < 3) ? 1 : (lane < 6) ? 2 : (lane < 9) ? 3 : (lane < 12) ? 5 : 4;
        atomicAdd(&s_part[s], (double)(diff * diff));
    }
    if (lane == 0) {
        atomicAdd(&s_part[6], (double)sla);
        int cls = g_cls[it];
        float ce = g_logZ[ip] - pred[ip * DD + cls];
        atomicAdd(&s_part[0], (double)ce);
    }
    __syncthreads();
    if (threadIdx.x < 7) atomicAdd(&g_acc[threadIdx.x], s_part[threadIdx.x]);
}

// ---------------- finalize ----------------
__global__ void finalize_kernel(float* out, int out_size)
{
    if (threadIdx.x == 0) {
        double denom = 32768.0 + 1e-8;
        double tot = 0.0;
        double st[7];
        for (int i = 0; i < 7; i++) { st[i] = g_acc[i]; tot += st[i]; }
        if (out_size >= 1) out[0] = (float)(tot / denom);
        for (int i = 0; i < 7; i++)
            if (out_size > i + 1) out[i + 1] = (float)(st[i] / denom);
    }
}

// ---------------- launch ----------------
extern "C" void kernel_launch(void* const* d_in, const int* in_sizes, int n_in,
                              void* d_out, int out_size)
{
    const float* pred   = (const float*)d_in[0];
    const float* target = (const float*)d_in[1];

    const int dynBytes = (16384 + 2*16*TSTRIDE) * 4;   // 82944
    cudaFuncSetAttribute(cost_lsa_kernel, cudaFuncAttributeMaxDynamicSharedMemorySize, dynBytes);

    prep_kernel<<<(2*TOK)/8, 256>>>(pred, target);
    cost_lsa_kernel<<<BB, 256, dynBytes>>>(pred);
    loss_kernel<<<TOK/8, 256>>>(pred);
    finalize_kernel<<<1, 32>>>((float*)d_out, out_size);
}

// round 17
// speedup vs baseline: 1.2604x; 1.0528x over previous
#include <cuda_runtime.h>
#include <math.h>
#include <stdint.h>

#define BB 256
#define NN 128
#define DD 564
#define NCLS 31
#define KP 544          // padded quadratic-dim count (512 lat + 18 smalls + 14 pad)
#define TOK (BB*NN)
#define TSTRIDE 136     // padded tile row stride (conflict-free mma fragment loads)

// ---------------- device scratch (static: allocations are forbidden) ----------------
__device__ float  g_vp[TOK*KP];
__device__ float  g_vt[TOK*KP];
__device__ float  g_n2p[TOK];
__device__ float  g_n2t[TOK];
__device__ float  g_logZ[TOK];
__device__ int    g_cls[TOK];
__device__ int    g_rows[TOK];
__device__ double g_acc[7];

__device__ __forceinline__ unsigned fkey(float v) {
    unsigned u = __float_as_uint(v);
    return (u & 0x80000000u) ? ~u : (u | 0x80000000u);
}
__device__ __forceinline__ float unfkey(unsigned k) {
    return __uint_as_float((k & 0x80000000u) ? (k & 0x7fffffffu) : ~k);
}
__device__ __forceinline__ unsigned f2tf32(float x) {
    unsigned r;
    asm("cvt.rna.tf32.f32 %0, %1;" : "=r"(r) : "f"(x));
    return r;
}

// ---------------- prep ----------------
__global__ void prep_kernel(const float* __restrict__ pred, const float* __restrict__ target)
{
    if (blockIdx.x == 0 && threadIdx.x < 7) g_acc[threadIdx.x] = 0.0;

    int w    = (blockIdx.x * blockDim.x + threadIdx.x) >> 5;
    int lane = threadIdx.x & 31;
    bool isT = (w >= TOK);
    int tok  = isT ? (w - TOK) : w;

    const float* src = (isT ? target : pred) + (size_t)tok * DD;
    float*       dst = (isT ? g_vt : g_vp) + (size_t)tok * KP;

    const float s512 = 0.04419417382415922f;   // 1/sqrt(512)
    float ss = 0.f;

    const float2* s2 = (const float2*)(src + 46);
    float2*       d2 = (float2*)dst;
    #pragma unroll 4
    for (int i = lane; i < 256; i += 32) {
        float2 v = s2[i];
        float a = v.x * s512, c = v.y * s512;
        d2[i] = make_float2(a, c);
        ss = fmaf(a, a, ss);
        ss = fmaf(c, c, ss);
    }

    if (lane < 18) {
        int d = (lane < 9) ? (31 + lane) : ((lane < 12) ? (34 + lane) : (546 + lane));
        float sc = (lane < 12) ? 0.5773502691896258f : 0.4082482904638630f;
        float vv = src[d] * sc;
        dst[512 + lane] = vv;
        ss = fmaf(vv, vv, ss);
    } else {
        dst[512 + lane] = 0.f;
    }

    #pragma unroll
    for (int o = 16; o; o >>= 1) ss += __shfl_xor_sync(0xffffffffu, ss, o);
    if (lane == 0) (isT ? g_n2t : g_n2p)[tok] = ss;

    float v = (lane < NCLS) ? src[lane] : -INFINITY;
    if (isT) {
        float bv = v; int bi = (lane < NCLS) ? lane : NCLS;
        #pragma unroll
        for (int o = 16; o; o >>= 1) {
            float ov = __shfl_xor_sync(0xffffffffu, bv, o);
            int   oi = __shfl_xor_sync(0xffffffffu, bi, o);
            if (ov > bv || (ov == bv && oi < bi)) { bv = ov; bi = oi; }
        }
        if (lane == 0) g_cls[tok] = bi;
    } else {
        float m = v;
        #pragma unroll
        for (int o = 16; o; o >>= 1) m = fmaxf(m, __shfl_xor_sync(0xffffffffu, m, o));
        float e = (lane < NCLS) ? expf(v - m) : 0.f;
        #pragma unroll
        for (int o = 16; o; o >>= 1) e += __shfl_xor_sync(0xffffffffu, e, o);
        if (lane == 0) g_logZ[tok] = m + logf(e);
    }
}

// ---------------- fused cost(tf32 MMA) + JV-LSA: one block per batch ----------------
// dyn smem: C[128*128] floats, then tiles[2*16*TSTRIDE] floats
__global__ void __launch_bounds__(256, 2) cost_lsa_kernel(const float* __restrict__ pred)
{
    extern __shared__ __align__(16) float dyn[];
    float* C     = dyn;              // 16384 floats
    float* tiles = dyn + 16384;      // 4352 floats (also reused as class table)

    __shared__ float s_n2p[NN], s_n2t[NN], s_logZ[NN];
    __shared__ int   s_cls[NN];
    __shared__ int   p_sh[NN+1];
    __shared__ int   way_sh[NN+1];
    __shared__ int2  wv_sh[NN+1];
    __shared__ int   imin_sh[NN];
    __shared__ int   rs_sh[NN];
    __shared__ int   free_sh[NN];

    int b   = blockIdx.x;
    int tid = threadIdx.x;
    size_t base = (size_t)b * NN;

    if (tid < NN) {
        s_n2p[tid]  = g_n2p[base + tid];
        s_n2t[tid]  = g_n2t[base + tid];
        s_logZ[tid] = g_logZ[base + tid];
        s_cls[tid]  = g_cls[base + tid];
        rs_sh[tid]  = 0;
        p_sh[tid]   = 0;
    }
    if (tid == NN) p_sh[NN] = 0;

    // ---- GEMM via mma.sync tf32 ----
    int wrp = tid >> 5;
    int t5  = tid & 31;
    int qr  = t5 >> 2;
    int qc  = t5 & 3;
    int m0  = wrp * 16;

    float d[16][4];
    #pragma unroll
    for (int nt = 0; nt < 16; nt++)
        #pragma unroll
        for (int c = 0; c < 4; c++) d[nt][c] = 0.f;

    const float* vp = g_vp + base * KP;
    const float* vt = g_vt + base * KP;
    float* As = tiles;
    float* Bs = tiles + 16 * TSTRIDE;

    int r  = tid >> 1;
    int kc = (tid & 1) * 8;

    for (int k0 = 0; k0 < KP; k0 += 16) {
        __syncthreads();
        float4 a0 = *(const float4*)(vp + (size_t)r * KP + k0 + kc);
        float4 a1 = *(const float4*)(vp + (size_t)r * KP + k0 + kc + 4);
        float4 b0 = *(const float4*)(vt + (size_t)r * KP + k0 + kc);
        float4 b1 = *(const float4*)(vt + (size_t)r * KP + k0 + kc + 4);
        float av[8] = {a0.x,a0.y,a0.z,a0.w,a1.x,a1.y,a1.z,a1.w};
        float bv[8] = {b0.x,b0.y,b0.z,b0.w,b1.x,b1.y,b1.z,b1.w};
        #pragma unroll
        for (int i = 0; i < 8; i++) {
            As[(kc+i)*TSTRIDE + r] = __uint_as_float(f2tf32(av[i]));
            Bs[(kc+i)*TSTRIDE + r] = __uint_as_float(f2tf32(bv[i]));
        }
        __syncthreads();

        #pragma unroll
        for (int ks = 0; ks < 2; ks++) {
            int kb = ks * 8;
            unsigned fa0 = __float_as_uint(As[(kb+qc  )*TSTRIDE + m0 + qr    ]);
            unsigned fa1 = __float_as_uint(As[(kb+qc  )*TSTRIDE + m0 + qr + 8]);
            unsigned fa2 = __float_as_uint(As[(kb+qc+4)*TSTRIDE + m0 + qr    ]);
            unsigned fa3 = __float_as_uint(As[(kb+qc+4)*TSTRIDE + m0 + qr + 8]);
            #pragma unroll
            for (int nt = 0; nt < 16; nt++) {
                int n0 = nt * 8;
                unsigned fb0 = __float_as_uint(Bs[(kb+qc  )*TSTRIDE + n0 + qr]);
                unsigned fb1 = __float_as_uint(Bs[(kb+qc+4)*TSTRIDE + n0 + qr]);
                asm volatile(
                    "mma.sync.aligned.m16n8k8.row.col.f32.tf32.tf32.f32 "
                    "{%0,%1,%2,%3}, {%4,%5,%6,%7}, {%8,%9}, {%0,%1,%2,%3};"
                    : "+f"(d[nt][0]), "+f"(d[nt][1]), "+f"(d[nt][2]), "+f"(d[nt][3])
                    : "r"(fa0), "r"(fa1), "r"(fa2), "r"(fa3), "r"(fb0), "r"(fb1));
            }
        }
    }

    __syncthreads();
    for (int i = tid; i < NN * NCLS; i += 256) {
        int p = i / NCLS, c = i - p * NCLS;
        tiles[p*32 + c] = pred[(base + p) * DD + c];
    }
    __syncthreads();

    {
        int p0 = m0 + qr, p1 = p0 + 8;
        float zp0 = s_logZ[p0], np0 = s_n2p[p0];
        float zp1 = s_logZ[p1], np1 = s_n2p[p1];
        #pragma unroll
        for (int nt = 0; nt < 16; nt++) {
            int j0 = nt*8 + 2*qc, j1 = j0 + 1;
            int   c0 = s_cls[j0],  c1 = s_cls[j1];
            float t0 = s_n2t[j0],  t1 = s_n2t[j1];
            float cs00 = fminf(zp0 - tiles[p0*32 + c0], 18.420680743952367f);
            float cs01 = fminf(zp0 - tiles[p0*32 + c1], 18.420680743952367f);
            float cs10 = fminf(zp1 - tiles[p1*32 + c0], 18.420680743952367f);
            float cs11 = fminf(zp1 - tiles[p1*32 + c1], 18.420680743952367f);
            float2 r0 = make_float2(cs00 + np0 + t0 - 2.0f*d[nt][0],
                                    cs01 + np0 + t1 - 2.0f*d[nt][1]);
            float2 r1 = make_float2(cs10 + np1 + t0 - 2.0f*d[nt][2],
                                    cs11 + np1 + t1 - 2.0f*d[nt][3]);
            *(float2*)(C + p0*NN + j0) = r0;
            *(float2*)(C + p1*NN + j0) = r1;
        }
    }
    __syncthreads();

    // =================== JV LSA, warp 0 only ===================
    if (tid >= 32) return;
    int lane = tid;

    // ---- 1. column reduction ----
    float vreg[4];
    float cmin[4] = {INFINITY, INFINITY, INFINITY, INFINITY};
    int   cim[4]  = {0, 0, 0, 0};
    for (int i = 0; i < NN; i++) {
        const float* row = C + i * NN;
        #pragma unroll
        for (int k = 0; k < 4; k++) {
            float c = row[lane + 32*k];
            if (c < cmin[k]) { cmin[k] = c; cim[k] = i; }
        }
    }
    #pragma unroll
    for (int k = 0; k < 4; k++) {
        vreg[k] = cmin[k];
        imin_sh[lane + 32*k] = cim[k];
    }
    __syncwarp();

    if (lane == 0) {
        for (int j = NN - 1; j >= 0; j--) {
            int i1 = imin_sh[j];
            if (rs_sh[i1] == 0) { rs_sh[i1] = j + 1; p_sh[j + 1] = i1 + 1; }
        }
    }
    __syncwarp();

    // ---- 2. reduction transfer + free-row list ----
    int nfree = 0;
    for (int i = 0; i < NN; i++) {
        int j1 = rs_sh[i];
        if (j1 == 0) {
            if (lane == 0) free_sh[nfree] = i + 1;
            nfree++;
        } else {
            const float* row = C + i * NN;
            float best = INFINITY;
            #pragma unroll
            for (int k = 0; k < 4; k++) {
                int jm = lane + 32*k;
                float cur = (jm + 1 == j1) ? INFINITY : (row[jm] - vreg[k]);
                best = fminf(best, cur);
            }
            float mu = unfkey(__reduce_min_sync(0xffffffffu, fkey(best)));
            #pragma unroll
            for (int k = 0; k < 4; k++)
                if (lane + 32*k + 1 == j1) vreg[k] -= mu;
        }
    }
    __syncwarp();

    // ---- 2b. ARR: up to 4 passes, NO requeue, early-exit when a pass makes no progress ----
    for (int pass = 0; pass < 4 && nfree > 0; pass++) {
        int nf = 0;
        for (int kf = 0; kf < nfree; kf++) {
            int i = free_sh[kf];
            const float* row = C + (i - 1) * NN;
            // per-lane two smallest
            float v1 = INFINITY, v2 = INFINITY; int j1l = 0, j2l = 0;
            #pragma unroll
            for (int k = 0; k < 4; k++) {
                float cur = row[lane + 32*k] - vreg[k];
                int j = lane + 32*k + 1;
                if (cur < v1) { v2 = v1; j2l = j1l; v1 = cur; j1l = j; }
                else if (cur < v2) { v2 = cur; j2l = j; }
            }
            unsigned k1 = fkey(v1);
            unsigned gk1 = __reduce_min_sync(0xffffffffu, k1);
            int j1 = (int)__reduce_min_sync(0xffffffffu, (k1 == gk1) ? (unsigned)j1l : 0xffffffffu);
            bool own = (j1l == j1);
            float cv = own ? v2 : v1;
            int   cj = own ? j2l : j1l;
            unsigned k2 = fkey(cv);
            unsigned gk2 = __reduce_min_sync(0xffffffffu, k2);
            int j2 = (int)__reduce_min_sync(0xffffffffu, (k2 == gk2) ? (unsigned)cj : 0xffffffffu);
            float umin = unfkey(gk1), usub = unfkey(gk2);

            int i0 = p_sh[j1];
            if (umin < usub) {
                float dd = usub - umin;
                #pragma unroll
                for (int k = 0; k < 4; k++)
                    if (lane + 32*k + 1 == j1) vreg[k] -= dd;
            } else if (i0 > 0) {
                j1 = j2; i0 = p_sh[j2];
            }
            if (lane == 0) p_sh[j1] = i;
            if (i0 > 0) {
                if (lane == 0) free_sh[nf] = i0;   // write idx <= read idx: safe in-place
                nf++;
            }
            __syncwarp();
        }
        if (nf == nfree) { nfree = nf; break; }   // no progress: further passes are no-ops
        nfree = nf;
        __syncwarp();
    }
    __syncwarp();

    // ---- 3. Dijkstra augmentation for remaining free rows ----
    for (int f = 0; f < nfree; f++) {
        int frow = free_sh[f];
        #pragma unroll
        for (int k = 0; k < 4; k++) {
            int j0m = lane + 32*k;
            int j   = j0m + 1;
            int pj  = p_sh[j];
            int off = pj ? (pj - 1) * NN : -1;
            float wv = pj ? (C[(pj - 1) * NN + j0m] - vreg[k]) : 0.f;
            wv_sh[j] = make_int2(off, __float_as_int(wv));
            way_sh[j] = 0;
        }
        if (lane == 0) p_sh[0] = frow;
        __syncwarp();

        const float* rowf = C + (frow - 1) * NN;
        float minv[4];
        #pragma unroll
        for (int k = 0; k < 4; k++) minv[k] = rowf[lane + 32*k] - vreg[k];

        unsigned used = 0;
        float minVal; int sink;
        while (true) {
            float bv = INFINITY; int bj = 0x7fffffff;
            #pragma unroll
            for (int k = 0; k < 4; k++) {
                float cand = ((used >> k) & 1) ? INFINITY : minv[k];
                if (cand < bv) { bv = cand; bj = lane + 32*k + 1; }
            }
            unsigned kk = fkey(bv);
            unsigned mk = __reduce_min_sync(0xffffffffu, kk);
            int j0 = (int)__reduce_min_sync(0xffffffffu, (kk == mk) ? (unsigned)bj : 0xffffffffu);
            minVal = unfkey(mk);

            int2 wv = wv_sh[j0];
            if (wv.x < 0) { sink = j0; break; }
            if (((j0 - 1) & 31) == lane) used |= 1u << ((j0 - 1) >> 5);

            const float* rowi = C + wv.x;
            float r0 = minVal - __int_as_float(wv.y);
            #pragma unroll
            for (int k = 0; k < 4; k++) {
                if (!((used >> k) & 1)) {
                    float cur = r0 + rowi[lane + 32*k] - vreg[k];
                    if (cur < minv[k]) { minv[k] = cur; way_sh[lane + 32*k + 1] = j0; }
                }
            }
        }
        __syncwarp();
        #pragma unroll
        for (int k = 0; k < 4; k++)
            if ((used >> k) & 1) vreg[k] -= (minVal - minv[k]);
        if (lane == 0) {
            int jj = sink;
            while (jj) { int w = way_sh[jj]; p_sh[jj] = p_sh[w]; jj = w; }
        }
        __syncwarp();
    }

    #pragma unroll
    for (int k = 0; k < 4; k++) {
        int j = lane + 32*k;
        g_rows[b*NN + j] = p_sh[j + 1] - 1;
    }
}

// ---------------- matched loss ----------------
__global__ void loss_kernel(const float* __restrict__ pred)
{
    __shared__ double s_part[7];
    if (threadIdx.x < 7) s_part[threadIdx.x] = 0.0;
    __syncthreads();

    int gw   = (blockIdx.x * blockDim.x + threadIdx.x) >> 5;
    int lane = threadIdx.x & 31;
    int b = gw >> 7;
    int r = g_rows[gw];
    size_t ip = (size_t)b * NN + r;
    size_t it = (size_t)gw;

    const float4* vp = (const float4*)(g_vp + ip * KP);
    const float4* vt = (const float4*)(g_vt + it * KP);

    float sla = 0.f;
    #pragma unroll
    for (int i = 0; i < 4; i++) {
        float4 a = vp[lane + 32*i];
        float4 c = vt[lane + 32*i];
        float dx = a.x - c.x, dy = a.y - c.y, dz = a.z - c.z, dw = a.w - c.w;
        sla = fmaf(dx, dx, sla); sla = fmaf(dy, dy, sla);
        sla = fmaf(dz, dz, sla); sla = fmaf(dw, dw, sla);
    }
    #pragma unroll
    for (int o = 16; o; o >>= 1) sla += __shfl_xor_sync(0xffffffffu, sla, o);

    if (lane < 18) {
        float diff = g_vp[ip*KP + 512 + lane] - g_vt[it*KP + 512 + lane];
        int s = (lane < 3) ? 1 : (lane < 6) ? 2 : (lane < 9) ? 3 : (lane < 12) ? 5 : 4;
        atomicAdd(&s_part[s], (double)(diff * diff));
    }
    if (lane == 0) {
        atomicAdd(&s_part[6], (double)sla);
        int cls = g_cls[it];
        float ce = g_logZ[ip] - pred[ip * DD + cls];
        atomicAdd(&s_part[0], (double)ce);
    }
    __syncthreads();
    if (threadIdx.x < 7) atomicAdd(&g_acc[threadIdx.x], s_part[threadIdx.x]);
}

// ---------------- finalize ----------------
__global__ void finalize_kernel(float* out, int out_size)
{
    if (threadIdx.x == 0) {
        double denom = 32768.0 + 1e-8;
        double tot = 0.0;
        double st[7];
        for (int i = 0; i < 7; i++) { st[i] = g_acc[i]; tot += st[i]; }
        if (out_size >= 1) out[0] = (float)(tot / denom);
        for (int i = 0; i < 7; i++)
            if (out_size > i + 1) out[i + 1] = (float)(st[i] / denom);
    }
}

// ---------------- launch ----------------
extern "C" void kernel_launch(void* const* d_in, const int* in_sizes, int n_in,
                              void* d_out, int out_size)
{
    const float* pred   = (const float*)d_in[0];
    const float* target = (const float*)d_in[1];

    const int dynBytes = (16384 + 2*16*TSTRIDE) * 4;   // 82944
    cudaFuncSetAttribute(cost_lsa_kernel, cudaFuncAttributeMaxDynamicSharedMemorySize, dynBytes);

    prep_kernel<<<(2*TOK)/8, 256>>>(pred, target);
    cost_lsa_kernel<<<BB, 256, dynBytes>>>(pred);
    loss_kernel<<<TOK/8, 256>>>(pred);
    finalize_kernel<<<1, 32>>>((float*)d_out, out_size);
}